// round 13
// baseline (speedup 1.0000x reference)
#include <cuda_runtime.h>
#include <cuda_bf16.h>
#include <cstdint>

#define NT 512
#define VB 128
#define TS 24

// weights in bf16 B-frag layout (prep kernel output)
__device__ uint32_t g_whF[4 * 6144];
__device__ uint32_t g_wiF[3 * 6144];
// layer-3 output fp32, head layout [t][j][v_global] = 100 MB
__device__ float g_act2[TS * 64 * 16384];

// ---- smem float offsets ----
#define S_RING 0       // 4 x 4096 fl: per-layer h bf16 A-frag tile (single parity)
#define S_HPF  16384   // 16 warps x 32 lanes x 66 fl = 33792 (fp32 h carry, excl. owned)
#define S_VIN  50176   // 3072  vin[t][v]
#define S_BS   53248   // 4 x 256 fused biases
#define S_W0   54272   // 192 layer-0 rank-1 ih weights
#define SMEM_FLOATS 54464   // 217,856 B

static __device__ __forceinline__ uint32_t pkbf(float lo, float hi) {
    __nv_bfloat162 b = __float22bfloat162_rn(make_float2(lo, hi));
    return *(uint32_t*)&b;
}
static __device__ __forceinline__ float tanha(float x) {
    float y; asm("tanh.approx.f32 %0, %1;" : "=f"(y) : "f"(x)); return y;
}
static __device__ __forceinline__ float sigt(float x) {
    return fmaf(tanha(0.5f * x), 0.5f, 0.5f);
}
#define MMAB(c, a, b) asm volatile( \
    "mma.sync.aligned.m16n8k16.row.col.f32.bf16.bf16.f32 " \
    "{%0,%1,%2,%3},{%4,%5,%6,%7},{%8,%9},{%0,%1,%2,%3};" \
    : "+f"((c)[0]), "+f"((c)[1]), "+f"((c)[2]), "+f"((c)[3]) \
    : "r"((a).x), "r"((a).y), "r"((a).z), "r"((a).w), "r"((b).x), "r"((b).y))

// ---- prep: convert GRU weights to bf16 B-frag global arrays ----
__global__ void __launch_bounds__(512)
prep_kernel(const float* __restrict__ wih0, const float* __restrict__ whh0,
            const float* __restrict__ wihL, const float* __restrict__ whhL)
{
    int idx = blockIdx.x * 512 + threadIdx.x;
    if (idx >= 43008) return;
    const float* W;
    uint32_t* dst;
    int i;
    if (idx < 24576) {
        int l = idx / 6144; i = idx % 6144;
        W = (l == 0) ? whh0 : whhL + (l - 1) * 12288;
        dst = g_whF + l * 6144 + i;
    } else {
        int r = idx - 24576;
        int l = r / 6144; i = r % 6144;
        W = wihL + l * 12288;
        dst = g_wiF + l * 6144 + i;
    }
    int gt = i >> 8, kt2 = (i >> 6) & 3, ln = (i >> 1) & 31, br = i & 1;
    int g = gt * 8 + (ln >> 2);
    int k = kt2 * 16 + (ln & 3) * 2 + br * 8;
    *dst = pkbf(W[g * 64 + k], W[g * 64 + k + 1]);
}

__global__ void __launch_bounds__(NT)
fused_rnn_kernel(const float* __restrict__ x,   const int*   __restrict__ lengths,
                 const float* __restrict__ sf,  const float* __restrict__ bp,
                 const float* __restrict__ wih0,const float* __restrict__ whh0,
                 const float* __restrict__ bih0,const float* __restrict__ bhh0,
                 const float* __restrict__ wihL,const float* __restrict__ whhL,
                 const float* __restrict__ bihL,const float* __restrict__ bhhL,
                 const float* __restrict__ bng, const float* __restrict__ bnb,
                 const float* __restrict__ bnm, const float* __restrict__ bnv,
                 const float* __restrict__ fcW, const float* __restrict__ fcb,
                 const float* __restrict__ fcWo,const float* __restrict__ fcbo,
                 float* __restrict__ out)
{
    extern __shared__ float sm[];
    const int tid = threadIdx.x;
    const int lane = tid & 31, w = tid >> 5;
    const int L = w >> 2, mg = w & 3;            // warp's layer + voxel group
    const int gq = lane >> 2, cc = lane & 3;
    const int blk = blockIdx.x;
    const int vbase = blk * VB;
    const int n  = vbase >> 12;
    const int sb = vbase & 4095;

    // ---- staging ----
    for (int l = 0; l < 4; ++l) {
        const float* Bi = (l == 0) ? bih0 : bihL + (l - 1) * 192;
        const float* Bh = (l == 0) ? bhh0 : bhhL + (l - 1) * 192;
        if (tid < 64) {
            int j = tid;
            sm[S_BS + l * 256 + j]       = Bi[j] + Bh[j];
            sm[S_BS + l * 256 + 64 + j]  = Bi[64 + j] + Bh[64 + j];
            sm[S_BS + l * 256 + 128 + j] = Bh[128 + j];
            sm[S_BS + l * 256 + 192 + j] = Bi[128 + j];
        }
    }
    if (tid < 192) sm[S_W0 + tid] = wih0[tid];
    for (int idx = tid; idx < TS * VB; idx += NT) {   // vin[t][v]
        int t = idx >> 7, v = idx & 127;
        int p = t % 3;
        sm[S_VIN + idx] = x[n * 98304 + t * 4096 + sb + v] * sf[p] + bp[p];
    }
    __syncthreads();

    // ---- pipelined wavefront: macro-step s, layer L processes t = s - L ----
    const uint2* WHg = (const uint2*)(g_whF + L * 6144);
    const uint2* WIg = (const uint2*)(g_wiF + (L - 1) * 6144);   // valid only L>0
    const uint4* hring = (const uint4*)(sm + S_RING + L * 4096);
    const uint4* xring = (const uint4*)(sm + S_RING + (L - 1) * 4096);
    uint4*       wring = (uint4*)(sm + S_RING + L * 4096);
    float*       hpfL  = sm + S_HPF + (w * 32 + lane) * 66;
    const float* BS    = sm + S_BS + L * 256;

    for (int s = 0; s < TS + 3; ++s) {
        const int t = s - L;
        const bool act = (t >= 0) && (t < TS);

        if (act) {
            // ---- phase 1: MMAs + combine (all ring READS; hpf excl-owned) ----
            #pragma unroll
            for (int c = 0; c < 4; ++c) {
                float cr[4][4], cz[4][4], cnh[4][4], cnx[4][4];
                #pragma unroll
                for (int f = 0; f < 4; ++f)
                    #pragma unroll
                    for (int q = 0; q < 4; ++q) {
                        cr[f][q] = 0.f; cz[f][q] = 0.f;
                        cnh[f][q] = 0.f; cnx[f][q] = 0.f;
                    }
                #pragma unroll
                for (int kt2 = 0; kt2 < 4; ++kt2) {
                    uint2 bh[6], bi2[6];
                    #pragma unroll
                    for (int ji = 0; ji < 2; ++ji) {
                        int jt = 2 * c + ji;
                        bh[ji*3+0] = WHg[((jt)      * 4 + kt2) * 32 + lane];
                        bh[ji*3+1] = WHg[((8 + jt)  * 4 + kt2) * 32 + lane];
                        bh[ji*3+2] = WHg[((16 + jt) * 4 + kt2) * 32 + lane];
                        if (L > 0) {
                            bi2[ji*3+0] = WIg[((jt)      * 4 + kt2) * 32 + lane];
                            bi2[ji*3+1] = WIg[((8 + jt)  * 4 + kt2) * 32 + lane];
                            bi2[ji*3+2] = WIg[((16 + jt) * 4 + kt2) * 32 + lane];
                        }
                    }
                    #pragma unroll
                    for (int mi = 0; mi < 2; ++mi) {
                        int mt = 2 * mg + mi;
                        if (t > 0) {
                            uint4 ah = hring[(mt * 4 + kt2) * 32 + lane];
                            #pragma unroll
                            for (int ji = 0; ji < 2; ++ji) {
                                int f = mi * 2 + ji;
                                MMAB(cr[f],  ah, bh[ji*3+0]);
                                MMAB(cz[f],  ah, bh[ji*3+1]);
                                MMAB(cnh[f], ah, bh[ji*3+2]);
                            }
                        }
                        if (L > 0) {
                            uint4 ax = xring[(mt * 4 + kt2) * 32 + lane];
                            #pragma unroll
                            for (int ji = 0; ji < 2; ++ji) {
                                int f = mi * 2 + ji;
                                MMAB(cr[f],  ax, bi2[ji*3+0]);
                                MMAB(cz[f],  ax, bi2[ji*3+1]);
                                MMAB(cnx[f], ax, bi2[ji*3+2]);
                            }
                        }
                    }
                }
                // combine chunk c (thread-local; h carry via exclusive smem fp32)
                #pragma unroll
                for (int mi = 0; mi < 2; ++mi) {
                    #pragma unroll
                    for (int ji = 0; ji < 2; ++ji) {
                        int f = mi * 2 + ji;
                        int hidx = c * 16 + f * 4;
                        float2 hp01 = make_float2(0.f, 0.f), hp23 = make_float2(0.f, 0.f);
                        if (t > 0) {
                            hp01 = *(const float2*)(hpfL + hidx);
                            hp23 = *(const float2*)(hpfL + hidx + 2);
                        }
                        float hpv[4] = {hp01.x, hp01.y, hp23.x, hp23.y};
                        float hv[4];
                        #pragma unroll
                        for (int q = 0; q < 4; ++q) {
                            int j = 16 * c + 8 * ji + 2 * cc + (q & 1);
                            int v = (2 * mg + mi) * 16 + gq + 8 * (q >> 1);
                            float xr = 0.f, xz = 0.f, xn;
                            if (L == 0) {
                                float xv = sm[S_VIN + t * VB + v];
                                xr = xv * sm[S_W0 + j];
                                xz = xv * sm[S_W0 + 64 + j];
                                xn = xv * sm[S_W0 + 128 + j] + BS[192 + j];
                            } else {
                                xn = cnx[f][q] + BS[192 + j];
                            }
                            float r  = sigt(cr[f][q] + xr + BS[j]);
                            float z  = sigt(cz[f][q] + xz + BS[64 + j]);
                            float nn = tanha(xn + r * (cnh[f][q] + BS[128 + j]));
                            float hnv = (1.f - z) * nn + z * hpv[q];
                            hv[q] = hnv;
                            if (L == 3)
                                g_act2[((size_t)(t * 64 + j) << 14) + vbase + v] = hnv;
                        }
                        *(float2*)(hpfL + hidx)     = make_float2(hv[0], hv[1]);
                        *(float2*)(hpfL + hidx + 2) = make_float2(hv[2], hv[3]);
                    }
                }
            }
        }
        __syncthreads();   // all ring reads done

        if (act) {
            // ---- phase 2: repack h from hpf (fp32) into ring bf16 A-frags ----
            #pragma unroll
            for (int c = 0; c < 4; ++c) {
                #pragma unroll
                for (int mi = 0; mi < 2; ++mi) {
                    uint32_t rg[4];
                    #pragma unroll
                    for (int ji = 0; ji < 2; ++ji) {
                        int hidx = c * 16 + (mi * 2 + ji) * 4;
                        float2 a = *(const float2*)(hpfL + hidx);
                        float2 b = *(const float2*)(hpfL + hidx + 2);
                        rg[ji * 2 + 0] = pkbf(a.x, a.y);
                        rg[ji * 2 + 1] = pkbf(b.x, b.y);
                    }
                    wring[((2 * mg + mi) * 4 + c) * 32 + lane] =
                        make_uint4(rg[0], rg[1], rg[2], rg[3]);
                }
            }
        }
        __syncthreads();   // ring writes visible before next step's reads
    }

    // ---- head: sel = h[len-1]+h[len-4]; 5x (BN+SiLU+FC); BN+SiLU; out ----
    float* A = sm;            // [j][v] 64 x 128 (ring area, now dead)
    float* B = sm + 8192;
    float* WST = sm + 16384;  // fcW staging (hpf area, now dead)
    const int len = lengths[n];
    const int t1 = len - 1, t2 = len - 4;
    #pragma unroll
    for (int it = 0; it < 16; ++it) {
        int idx = tid + it * NT, v = idx & 127, j = idx >> 7;
        A[j * VB + v] = g_act2[((size_t)(t1 * 64 + j) << 14) + vbase + v]
                      + g_act2[((size_t)(t2 * 64 + j) << 14) + vbase + v];
    }
    __syncthreads();
    for (int i = 0; i < 5; ++i) {
        for (int idx = tid; idx < 4096; idx += NT) WST[idx] = fcW[i * 4096 + idx];
        #pragma unroll
        for (int it = 0; it < 16; ++it) {
            int idx = tid + it * NT, v = idx & 127, j = idx >> 7;
            float y = bng[i * 64 + j] * (A[j * VB + v] - bnm[i * 64 + j])
                      * rsqrtf(bnv[i * 64 + j] + 1e-5f) + bnb[i * 64 + j];
            A[j * VB + v] = y * sigt(y);
        }
        __syncthreads();
        #pragma unroll
        for (int it = 0; it < 16; ++it) {
            int idx = tid + it * NT, v = idx & 127, o = idx >> 7;
            float acc = fcb[i * 64 + o];
            #pragma unroll 8
            for (int j = 0; j < 64; ++j) acc += A[j * VB + v] * WST[o * 64 + j];
            B[o * VB + v] = acc;
        }
        __syncthreads();
        float* tswp = A; A = B; B = tswp;
    }
    #pragma unroll
    for (int it = 0; it < 16; ++it) {
        int idx = tid + it * NT, v = idx & 127, j = idx >> 7;
        float y = bng[5 * 64 + j] * (A[j * VB + v] - bnm[5 * 64 + j])
                  * rsqrtf(bnv[5 * 64 + j] + 1e-5f) + bnb[5 * 64 + j];
        A[j * VB + v] = y * sigt(y);
    }
    __syncthreads();
    if (tid < VB) {
        float acc = fcbo[0];
        #pragma unroll 8
        for (int j = 0; j < 64; ++j) acc += A[j * VB + tid] * fcWo[j];
        out[vbase + tid] = acc;
    }
}

extern "C" void kernel_launch(void* const* d_in, const int* in_sizes, int n_in,
                              void* d_out, int out_size)
{
    const float* x     = (const float*)d_in[0];
    const int*   lens  = (const int*)  d_in[1];
    const float* sf    = (const float*)d_in[2];
    const float* bp    = (const float*)d_in[3];
    const float* wih0  = (const float*)d_in[4];
    const float* whh0  = (const float*)d_in[5];
    const float* bih0  = (const float*)d_in[6];
    const float* bhh0  = (const float*)d_in[7];
    const float* wihL  = (const float*)d_in[8];
    const float* whhL  = (const float*)d_in[9];
    const float* bihL  = (const float*)d_in[10];
    const float* bhhL  = (const float*)d_in[11];
    const float* bng   = (const float*)d_in[12];
    const float* bnb   = (const float*)d_in[13];
    const float* bnm   = (const float*)d_in[14];
    const float* bnv   = (const float*)d_in[15];
    const float* fcW   = (const float*)d_in[16];
    const float* fcb   = (const float*)d_in[17];
    const float* fcWo  = (const float*)d_in[18];
    const float* fcbo  = (const float*)d_in[19];
    float* out = (float*)d_out;

    prep_kernel<<<84, 512>>>(wih0, whh0, wihL, whhL);

    const size_t smem = SMEM_FLOATS * sizeof(float);   // 217,856 B
    cudaFuncSetAttribute(fused_rnn_kernel,
                         cudaFuncAttributeMaxDynamicSharedMemorySize, (int)smem);
    fused_rnn_kernel<<<128, NT, smem>>>(
        x, lens, sf, bp, wih0, whh0, bih0, bhh0,
        wihL, whhL, bihL, bhhL, bng, bnb, bnm, bnv,
        fcW, fcb, fcWo, fcbo, out);
}

// round 14
// speedup vs baseline: 1.0062x; 1.0062x over previous
#include <cuda_runtime.h>
#include <cuda_bf16.h>
#include <cstdint>

#define NT 1024
#define VB 128
#define TS 24

// layers 0-2 activations as bf16 A-frag tiles: [t][blk][1024 x uint4] = 50 MB
__device__ uint4 g_actb[TS * 128 * 1024];
// layer-3 output fp32, head layout [t][j][v_global] = 100 MB
__device__ float g_act2[TS * 64 * 16384];

// ---- smem float offsets ----
// all-layer weight frags: L0 WH@0(6144); l>=1: WH@6144+(l-1)*12288, WI@WH+6144
#define S_W    0
#define S_H0   43008   // 4096 fl: h A-frag buf0 (1024 uint4)
#define S_H1   47104
#define S_VIN  51200   // 3072 vin[t][v]
#define S_BS   54272   // 4 x 256 fused biases
#define S_W0   55296   // 192 layer-0 rank-1 ih weights
#define SMEM_FLOATS 55488   // 221,952 B

static __device__ __forceinline__ uint32_t pkbf(float lo, float hi) {
    __nv_bfloat162 b = __float22bfloat162_rn(make_float2(lo, hi));
    return *(uint32_t*)&b;
}
static __device__ __forceinline__ float tanha(float x) {
    float y; asm("tanh.approx.f32 %0, %1;" : "=f"(y) : "f"(x)); return y;
}
static __device__ __forceinline__ float sigt(float x) {
    return fmaf(tanha(0.5f * x), 0.5f, 0.5f);
}
#define MMAB(c, a, b) asm volatile( \
    "mma.sync.aligned.m16n8k16.row.col.f32.bf16.bf16.f32 " \
    "{%0,%1,%2,%3},{%4,%5,%6,%7},{%8,%9},{%0,%1,%2,%3};" \
    : "+f"((c)[0]), "+f"((c)[1]), "+f"((c)[2]), "+f"((c)[3]) \
    : "r"((a).x), "r"((a).y), "r"((a).z), "r"((a).w), "r"((b).x), "r"((b).y))

// One GRU layer, 24 steps. Warp w (32 warps): mg=w&3 (voxels 32mg..32mg+31),
// ng=w>>2 (j 8ng..8ng+7). C-frags: 8 (32 regs); fp32 h carry in regs.
template<bool L0, bool LAST>
static __device__ void layer_run(float* __restrict__ sm, int tid, int blk,
                                 int whO, int wiO, int bsO)
{
    const int lane = tid & 31, w = tid >> 5;
    const int mg = w & 3, ng = w >> 2;
    const int gq = lane >> 2, cc = lane & 3;
    const int jt2 = ng >> 1, jh = ng & 1;        // ring uint4 slot + uint2 half
    const int vbase = blk * VB;
    const uint2* WHu = (const uint2*)(sm + whO);
    const uint2* WIu = (const uint2*)(sm + wiO);
    const float* BS = sm + bsO;
    float hp[8];
    #pragma unroll
    for (int i = 0; i < 8; ++i) hp[i] = 0.f;

    for (int t = 0; t < TS; ++t) {
        uint4*       hb_n = (uint4*)(sm + ((t & 1) ? S_H0 : S_H1));
        const uint4* hb_c = (const uint4*)(sm + ((t & 1) ? S_H1 : S_H0));

        float cr[2][4], cz[2][4], cnh[2][4], cnx[2][4];
        #pragma unroll
        for (int f = 0; f < 2; ++f)
            #pragma unroll
            for (int q = 0; q < 4; ++q) {
                cr[f][q] = 0.f; cz[f][q] = 0.f; cnh[f][q] = 0.f; cnx[f][q] = 0.f;
            }

        #pragma unroll
        for (int kt2 = 0; kt2 < 4; ++kt2) {
            uint2 bh0, bh1, bh2;
            bh0 = WHu[((ng)      * 4 + kt2) * 32 + lane];
            bh1 = WHu[((8 + ng)  * 4 + kt2) * 32 + lane];
            bh2 = WHu[((16 + ng) * 4 + kt2) * 32 + lane];
            #pragma unroll
            for (int mi = 0; mi < 2; ++mi) {
                int mt = 2 * mg + mi;
                if (t > 0) {
                    uint4 ah = hb_c[(mt * 4 + kt2) * 32 + lane];
                    MMAB(cr[mi],  ah, bh0);
                    MMAB(cz[mi],  ah, bh1);
                    MMAB(cnh[mi], ah, bh2);
                }
            }
            if (!L0) {
                uint2 bi0, bi1, bi2;
                bi0 = WIu[((ng)      * 4 + kt2) * 32 + lane];
                bi1 = WIu[((8 + ng)  * 4 + kt2) * 32 + lane];
                bi2 = WIu[((16 + ng) * 4 + kt2) * 32 + lane];
                #pragma unroll
                for (int mi = 0; mi < 2; ++mi) {
                    int mt = 2 * mg + mi;
                    uint4 ax = __ldcs(&g_actb[(size_t)(t * 128 + blk) * 1024
                                              + (mt * 4 + kt2) * 32 + lane]);
                    MMAB(cr[mi],  ax, bi0);
                    MMAB(cz[mi],  ax, bi1);
                    MMAB(cnx[mi], ax, bi2);
                }
            }
        }

        // thread-local combine; pack into uint2 half of the ring's uint4 slot
        #pragma unroll
        for (int mi = 0; mi < 2; ++mi) {
            int mt = 2 * mg + mi;
            float hv[4];
            #pragma unroll
            for (int q = 0; q < 4; ++q) {
                int j = 8 * ng + 2 * cc + (q & 1);
                int v = mt * 16 + gq + 8 * (q >> 1);
                float xr = 0.f, xz = 0.f, xn;
                if (L0) {
                    float xv = sm[S_VIN + t * VB + v];
                    xr = xv * sm[S_W0 + j];
                    xz = xv * sm[S_W0 + 64 + j];
                    xn = xv * sm[S_W0 + 128 + j] + BS[192 + j];
                } else {
                    xn = cnx[mi][q] + BS[192 + j];
                }
                float r  = sigt(cr[mi][q] + xr + BS[j]);
                float z  = sigt(cz[mi][q] + xz + BS[64 + j]);
                float nn = tanha(xn + r * (cnh[mi][q] + BS[128 + j]));
                float hnv = (1.f - z) * nn + z * hp[mi * 4 + q];
                hp[mi * 4 + q] = hnv;
                hv[q] = hnv;
                if (LAST)
                    __stcs(&g_act2[((size_t)(t * 64 + j) << 14) + vbase + v], hnv);
            }
            uint2 u = make_uint2(pkbf(hv[0], hv[1]), pkbf(hv[2], hv[3]));
            int slot = (mt * 4 + jt2) * 32 + lane;
            ((uint2*)hb_n)[slot * 2 + jh] = u;
            if (!LAST)
                __stcs(((uint2*)&g_actb[(size_t)(t * 128 + blk) * 1024]) + slot * 2 + jh, u);
        }
        __syncthreads();   // one barrier per step (double-buffered h)
    }
}

__global__ void __launch_bounds__(NT)
fused_rnn_kernel(const float* __restrict__ x,   const int*   __restrict__ lengths,
                 const float* __restrict__ sf,  const float* __restrict__ bp,
                 const float* __restrict__ wih0,const float* __restrict__ whh0,
                 const float* __restrict__ bih0,const float* __restrict__ bhh0,
                 const float* __restrict__ wihL,const float* __restrict__ whhL,
                 const float* __restrict__ bihL,const float* __restrict__ bhhL,
                 const float* __restrict__ bng, const float* __restrict__ bnb,
                 const float* __restrict__ bnm, const float* __restrict__ bnv,
                 const float* __restrict__ fcW, const float* __restrict__ fcb,
                 const float* __restrict__ fcWo,const float* __restrict__ fcbo,
                 float* __restrict__ out)
{
    extern __shared__ float sm[];
    const int tid = threadIdx.x;
    const int blk = blockIdx.x;
    const int vbase = blk * VB;
    const int n  = vbase >> 12;
    const int sb = vbase & 4095;

    // ---- stage ALL layers' weight B-frags + biases ----
    for (int l = 0; l < 4; ++l) {
        const float* Wh = (l == 0) ? whh0 : whhL + (l - 1) * 12288;
        const float* Wi = (l == 0) ? wih0 : wihL + (l - 1) * 12288;
        const float* Bi = (l == 0) ? bih0 : bihL + (l - 1) * 192;
        const float* Bh = (l == 0) ? bhh0 : bhhL + (l - 1) * 192;
        int whO = (l == 0) ? 0 : (6144 + (l - 1) * 12288);
        uint32_t* WHu = (uint32_t*)(sm + whO);
        uint32_t* WIu = WHu + 6144;
        for (int idx = tid; idx < 6144; idx += NT) {
            int gt = idx >> 8, kt2 = (idx >> 6) & 3, ln = (idx >> 1) & 31, br = idx & 1;
            int g = gt * 8 + (ln >> 2);
            int k = kt2 * 16 + (ln & 3) * 2 + br * 8;
            WHu[idx] = pkbf(Wh[g * 64 + k], Wh[g * 64 + k + 1]);
            if (l > 0) WIu[idx] = pkbf(Wi[g * 64 + k], Wi[g * 64 + k + 1]);
        }
        if (tid < 64) {
            int j = tid;
            sm[S_BS + l * 256 + j]       = Bi[j] + Bh[j];
            sm[S_BS + l * 256 + 64 + j]  = Bi[64 + j] + Bh[64 + j];
            sm[S_BS + l * 256 + 128 + j] = Bh[128 + j];
            sm[S_BS + l * 256 + 192 + j] = Bi[128 + j];
        }
    }
    if (tid < 192) sm[S_W0 + tid] = wih0[tid];
    for (int idx = tid; idx < TS * VB; idx += NT) {   // vin[t][v]
        int t = idx >> 7, v = idx & 127;
        int p = t % 3;
        sm[S_VIN + idx] = x[n * 98304 + t * 4096 + sb + v] * sf[p] + bp[p];
    }
    __syncthreads();

    layer_run<true , false>(sm, tid, blk, 0,     0,     S_BS);
    layer_run<false, false>(sm, tid, blk, 6144,  12288, S_BS + 256);
    layer_run<false, false>(sm, tid, blk, 18432, 24576, S_BS + 512);
    layer_run<false, true >(sm, tid, blk, 30720, 36864, S_BS + 768);
    __syncthreads();

    // ---- head: sel = h[len-1]+h[len-4]; 5x (BN+SiLU+FC); BN+SiLU; out ----
    float* A = sm;            // [j][v] 64 x 128 (weight region now dead)
    float* B = sm + 8192;
    float* WST = sm + 16384;  // fcW staging
    const int len = lengths[n];
    const int t1 = len - 1, t2 = len - 4;
    #pragma unroll
    for (int it = 0; it < 8; ++it) {
        int idx = tid + it * NT, v = idx & 127, j = idx >> 7;
        A[j * VB + v] = g_act2[((size_t)(t1 * 64 + j) << 14) + vbase + v]
                      + g_act2[((size_t)(t2 * 64 + j) << 14) + vbase + v];
    }
    __syncthreads();
    for (int i = 0; i < 5; ++i) {
        for (int idx = tid; idx < 4096; idx += NT) WST[idx] = fcW[i * 4096 + idx];
        #pragma unroll
        for (int it = 0; it < 8; ++it) {
            int idx = tid + it * NT, v = idx & 127, j = idx >> 7;
            float y = bng[i * 64 + j] * (A[j * VB + v] - bnm[i * 64 + j])
                      * rsqrtf(bnv[i * 64 + j] + 1e-5f) + bnb[i * 64 + j];
            A[j * VB + v] = y * sigt(y);
        }
        __syncthreads();
        #pragma unroll
        for (int it = 0; it < 8; ++it) {
            int idx = tid + it * NT, v = idx & 127, o = idx >> 7;
            float acc = fcb[i * 64 + o];
            #pragma unroll 8
            for (int j = 0; j < 64; ++j) acc += A[j * VB + v] * WST[o * 64 + j];
            B[o * VB + v] = acc;
        }
        __syncthreads();
        float* tswp = A; A = B; B = tswp;
    }
    #pragma unroll
    for (int it = 0; it < 8; ++it) {
        int idx = tid + it * NT, v = idx & 127, j = idx >> 7;
        float y = bng[5 * 64 + j] * (A[j * VB + v] - bnm[5 * 64 + j])
                  * rsqrtf(bnv[5 * 64 + j] + 1e-5f) + bnb[5 * 64 + j];
        A[j * VB + v] = y * sigt(y);
    }
    __syncthreads();
    if (tid < VB) {
        float acc = fcbo[0];
        #pragma unroll 8
        for (int j = 0; j < 64; ++j) acc += A[j * VB + tid] * fcWo[j];
        out[vbase + tid] = acc;
    }
}

extern "C" void kernel_launch(void* const* d_in, const int* in_sizes, int n_in,
                              void* d_out, int out_size)
{
    const float* x     = (const float*)d_in[0];
    const int*   lens  = (const int*)  d_in[1];
    const float* sf    = (const float*)d_in[2];
    const float* bp    = (const float*)d_in[3];
    const float* wih0  = (const float*)d_in[4];
    const float* whh0  = (const float*)d_in[5];
    const float* bih0  = (const float*)d_in[6];
    const float* bhh0  = (const float*)d_in[7];
    const float* wihL  = (const float*)d_in[8];
    const float* whhL  = (const float*)d_in[9];
    const float* bihL  = (const float*)d_in[10];
    const float* bhhL  = (const float*)d_in[11];
    const float* bng   = (const float*)d_in[12];
    const float* bnb   = (const float*)d_in[13];
    const float* bnm   = (const float*)d_in[14];
    const float* bnv   = (const float*)d_in[15];
    const float* fcW   = (const float*)d_in[16];
    const float* fcb   = (const float*)d_in[17];
    const float* fcWo  = (const float*)d_in[18];
    const float* fcbo  = (const float*)d_in[19];
    float* out = (float*)d_out;

    const size_t smem = SMEM_FLOATS * sizeof(float);   // 221,952 B
    cudaFuncSetAttribute(fused_rnn_kernel,
                         cudaFuncAttributeMaxDynamicSharedMemorySize, (int)smem);
    fused_rnn_kernel<<<128, NT, smem>>>(
        x, lens, sf, bp, wih0, whh0, bih0, bhh0,
        wihL, whhL, bihL, bhhL, bng, bnb, bnm, bnv,
        fcW, fcb, fcWo, fcbo, out);
}